// round 14
// baseline (speedup 1.0000x reference)
#include <cuda_runtime.h>
#include <cuda_bf16.h>
#include <cstdint>
#include <cstddef>

// ---------------- problem constants ----------------
#define BB 16
#define HWN 4096
#define KC 16
#define FF 576
#define OO 64
#define RR 8
#define MLPD 32

// feature order: f' = tap*64 + c  (tap = 3*di+dj). Weights index original f = c*9+tap.

// ---------------- device scratch ----------------
__device__ __nv_bfloat16 g_img[BB * HWN * 128];      // 16.8 MB channel-last split image
__device__ __nv_bfloat16 g_kThi[BB * KC * OO * FF];  // kernels^T hi [bk][o][f']
__device__ __nv_bfloat16 g_kTlo[BB * KC * OO * FF];
__device__ float g_outT[BB * HWN * OO];              // [b][pos][o]
__device__ int   g_offs[BB * 17];
__device__ int   g_perm[BB * HWN];
__device__ int   g_inv[BB * HWN];
__device__ float g_lowrank[BB * KC * RR];
__device__ float g_biasv[BB * KC * OO];

// ---------------- helpers ----------------
__device__ __forceinline__ uint32_t smem_u32(const void* p) {
    return (uint32_t)__cvta_generic_to_shared(p);
}
#define CP16(dst, src) asm volatile("cp.async.cg.shared.global [%0], [%1], 16;" :: "r"(dst), "l"(src))
#define CP16Z(dst, src, sz) asm volatile("cp.async.cg.shared.global [%0], [%1], 16, %2;" :: "r"(dst), "l"(src), "r"(sz))
#define CP_COMMIT()    asm volatile("cp.async.commit_group;")
#define CP_WAIT(n)     asm volatile("cp.async.wait_group %0;" :: "n"(n))

__device__ __forceinline__ void bsplit(float v, unsigned short& h, unsigned short& l) {
    __nv_bfloat16 hb = __float2bfloat16(v);
    float res = v - __bfloat162float(hb);
    __nv_bfloat16 lb = __float2bfloat16(res);
    h = *reinterpret_cast<unsigned short*>(&hb);
    l = *reinterpret_cast<unsigned short*>(&lb);
}

#define MMA_BF16(d, a, b) \
    asm volatile("mma.sync.aligned.m16n8k16.row.col.f32.bf16.bf16.f32 " \
        "{%0,%1,%2,%3}, {%4,%5,%6,%7}, {%8,%9}, {%0,%1,%2,%3};" \
        : "+f"((d)[0]), "+f"((d)[1]), "+f"((d)[2]), "+f"((d)[3]) \
        : "r"((a)[0]), "r"((a)[1]), "r"((a)[2]), "r"((a)[3]), \
          "r"((b)[0]), "r"((b)[1]))

#define LDSM_X4(r, addr) \
    asm volatile("ldmatrix.sync.aligned.m8n8.x4.shared.b16 {%0,%1,%2,%3}, [%4];" \
        : "=r"((r)[0]), "=r"((r)[1]), "=r"((r)[2]), "=r"((r)[3]) : "r"(addr))
#define LDSM_X2(r, addr) \
    asm volatile("ldmatrix.sync.aligned.m8n8.x2.shared.b16 {%0,%1}, [%2];" \
        : "=r"((r)[0]), "=r"((r)[1]) : "r"(addr))

// ================= K1: convert x -> channel-last split image + count/scatter =================
// grid (64 y, 16 b), block 256
__global__ void convert_count_kernel(const float* __restrict__ x, const int* __restrict__ labels) {
    __shared__ float sm[64 * 65];
    const int y = blockIdx.x, b = blockIdx.y;
    const int tid = threadIdx.x;

    for (int idx = tid; idx < 4096; idx += 256) {
        int c = idx >> 6, xx = idx & 63;
        sm[xx * 65 + c] = x[(((size_t)(b * 64 + c)) << 12) + (y << 6) + xx];
    }
    __syncthreads();

    {
        const int xx = tid >> 2, cq = tid & 3;
        const float* row = sm + xx * 65 + cq * 16;
        unsigned short hu[16], lu[16];
#pragma unroll
        for (int i = 0; i < 16; i++) bsplit(row[i], hu[i], lu[i]);
        __nv_bfloat16* dst = g_img + (((size_t)(b << 12) + (y << 6) + xx) << 7);
        uint4 ph0, ph1, pl0, pl1;
        ph0.x = (uint32_t)hu[0] | ((uint32_t)hu[1] << 16);   ph0.y = (uint32_t)hu[2] | ((uint32_t)hu[3] << 16);
        ph0.z = (uint32_t)hu[4] | ((uint32_t)hu[5] << 16);   ph0.w = (uint32_t)hu[6] | ((uint32_t)hu[7] << 16);
        ph1.x = (uint32_t)hu[8] | ((uint32_t)hu[9] << 16);   ph1.y = (uint32_t)hu[10] | ((uint32_t)hu[11] << 16);
        ph1.z = (uint32_t)hu[12] | ((uint32_t)hu[13] << 16); ph1.w = (uint32_t)hu[14] | ((uint32_t)hu[15] << 16);
        pl0.x = (uint32_t)lu[0] | ((uint32_t)lu[1] << 16);   pl0.y = (uint32_t)lu[2] | ((uint32_t)lu[3] << 16);
        pl0.z = (uint32_t)lu[4] | ((uint32_t)lu[5] << 16);   pl0.w = (uint32_t)lu[6] | ((uint32_t)lu[7] << 16);
        pl1.x = (uint32_t)lu[8] | ((uint32_t)lu[9] << 16);   pl1.y = (uint32_t)lu[10] | ((uint32_t)lu[11] << 16);
        pl1.z = (uint32_t)lu[12] | ((uint32_t)lu[13] << 16); pl1.w = (uint32_t)lu[14] | ((uint32_t)lu[15] << 16);
        *reinterpret_cast<uint4*>(dst + cq * 16)          = ph0;
        *reinterpret_cast<uint4*>(dst + cq * 16 + 8)      = ph1;
        *reinterpret_cast<uint4*>(dst + 64 + cq * 16)     = pl0;
        *reinterpret_cast<uint4*>(dst + 64 + cq * 16 + 8) = pl1;
    }

    if (blockIdx.x == 0) {
        __shared__ int cnt[KC];
        __shared__ int offs[KC];
        const int lane = tid & 31;
        if (tid < KC) cnt[tid] = 0;
        __syncthreads();
        for (int n = tid; n < HWN; n += 256) {
            int k = labels[b * HWN + n];
            unsigned mask = __match_any_sync(0xffffffffu, k);
            if (lane == (__ffs(mask) - 1)) atomicAdd(&cnt[k], __popc(mask));
        }
        __syncthreads();
        if (tid == 0) {
            int off = 0;
            for (int k = 0; k < KC; k++) {
                g_offs[b * 17 + k] = off;
                offs[k] = off;
                off += cnt[k];
            }
            g_offs[b * 17 + 16] = off;
        }
        __syncthreads();
        if (tid < KC) cnt[tid] = offs[tid];
        __syncthreads();
        for (int n = tid; n < HWN; n += 256) {
            int k = labels[b * HWN + n];
            unsigned mask = __match_any_sync(0xffffffffu, k);
            int leader = __ffs(mask) - 1;
            int rank = __popc(mask & ((1u << lane) - 1u));
            int base = 0;
            if (lane == leader) base = atomicAdd(&cnt[k], __popc(mask));
            base = __shfl_sync(0xffffffffu, base, leader);
            g_perm[b * HWN + base + rank] = n;
            g_inv[b * HWN + n] = base + rank;
        }
    }
}

// ================= K2: centers (8-way row-parallel, uint4 gathers) + fused MLPs =================
// grid 256 (= bk), block 576 = 8 row-groups x 72 threads
__global__ void centers_mlp_kernel(const float* __restrict__ lr_w1, const float* __restrict__ lr_b1,
                                   const float* __restrict__ lr_w2, const float* __restrict__ lr_b2,
                                   const float* __restrict__ lr_w3, const float* __restrict__ lr_b3,
                                   const float* __restrict__ bw1,   const float* __restrict__ bb1,
                                   const float* __restrict__ bw2,   const float* __restrict__ bb2) {
    __shared__ float part[8][FF];
    __shared__ float cs[FF];
    __shared__ float p1[18][33], p2[18][33];
    __shared__ float h1[MLPD], h2[MLPD], t1v[MLPD];
    const int bk = blockIdx.x;
    const int b = bk >> 4;
    const int off = g_offs[bk + b];
    const int end = g_offs[bk + b + 1];
    const int nk = end - off;
    const int t = threadIdx.x;
    const int* __restrict__ pm = g_perm + (b << 12) + off;

    {
        const int rg = t / 72;
        const int ft = t - rg * 72;
        const int tap = ft >> 3;
        const int dy = tap / 3 - 1, dx = tap % 3 - 1;
        const int c8 = (ft & 7) << 3;
        const __nv_bfloat16* img = g_img + (((size_t)b << 12) << 7);
        float acc[8];
#pragma unroll
        for (int q = 0; q < 8; q++) acc[q] = 0.f;
        for (int r = rg; r < nk; r += 8) {
            int n = pm[r];
            int yy = (n >> 6) + dy, xx = (n & 63) + dx;
            if (((unsigned)yy < 64u) && ((unsigned)xx < 64u)) {
                const __nv_bfloat16* p = img + (((yy << 6) + xx) << 7) + c8;
                uint4 hp = *reinterpret_cast<const uint4*>(p);
                uint4 lp = *reinterpret_cast<const uint4*>(p + 64);
                const __nv_bfloat162* h2v = reinterpret_cast<const __nv_bfloat162*>(&hp);
                const __nv_bfloat162* l2v = reinterpret_cast<const __nv_bfloat162*>(&lp);
#pragma unroll
                for (int w = 0; w < 4; w++) {
                    float2 hv = __bfloat1622float2(h2v[w]);
                    float2 lv = __bfloat1622float2(l2v[w]);
                    acc[w * 2]     += hv.x + lv.x;
                    acc[w * 2 + 1] += hv.y + lv.y;
                }
            }
        }
        const int fb = tap * 64 + c8;
#pragma unroll
        for (int q = 0; q < 8; q++) part[rg][fb + q] = acc[q];
    }
    __syncthreads();
    if (t < 144) {
        const float inv = 1.0f / ((float)nk + 1e-6f);
#pragma unroll
        for (int q = 0; q < 4; q++) {
            int e = t * 4 + q;
            float s = part[0][e] + part[1][e] + part[2][e] + part[3][e]
                    + part[4][e] + part[5][e] + part[6][e] + part[7][e];
            cs[e] = s * inv;
        }
    }
    __syncthreads();

    {
        const int j = t & 31, prt = t >> 5;
        float s = 0.f, s2 = 0.f;
        for (int fp = prt * 32; fp < prt * 32 + 32; fp++) {
            float cv = cs[fp];
            int f = (fp & 63) * 9 + (fp >> 6);
            s  += cv * lr_w1[f * MLPD + j];
            s2 += cv * bw1[f * MLPD + j];
        }
        p1[prt][j] = s;
        p2[prt][j] = s2;
    }
    __syncthreads();
    if (t < MLPD) {
        float s = lr_b1[t], s2 = bb1[t];
#pragma unroll
        for (int p = 0; p < 18; p++) { s += p1[p][t]; s2 += p2[p][t]; }
        h1[t]  = fmaxf(s, 0.f);
        t1v[t] = fmaxf(s2, 0.f);
    }
    __syncthreads();
    if (t < MLPD) {
        float s = lr_b2[t];
        for (int i = 0; i < MLPD; i++) s += h1[i] * lr_w2[i * MLPD + t];
        h2[t] = fmaxf(s, 0.f);
    }
    __syncthreads();
    if (t < RR) {
        float s = lr_b3[t];
        for (int i = 0; i < MLPD; i++) s += h2[i] * lr_w3[i * RR + t];
        g_lowrank[bk * RR + t] = s;
    }
    if (t < OO) {
        float s = bb2[t];
        for (int i = 0; i < MLPD; i++) s += t1v[i] * bw2[i * OO + t];
        g_biasv[bk * OO + t] = s;
    }
}

// ================= K3: fabricate kernels^T in f'-order =================
__global__ void buildk_kernel(const float* __restrict__ base) {
    __shared__ float bs[RR][16][65];
    __shared__ float lrs[16][RR];
    const int fb = blockIdx.x, gb = blockIdx.y;
    const int tap = fb >> 2;
    const int cbase = (fb & 3) * 16;
    const int f0p = fb * 16;
    const int tid = threadIdx.x;

    for (int idx = tid; idx < RR * 1024; idx += 256) {
        int r = idx >> 10;
        int e = idx & 1023;
        int fl = e >> 6, o = e & 63;
        int f = (cbase + fl) * 9 + tap;
        bs[r][fl][o] = base[((size_t)(r * FF + f)) * OO + o];
    }
    if (tid < 16 * RR)
        lrs[tid >> 3][tid & 7] = g_lowrank[(gb * 16 + (tid >> 3)) * RR + (tid & 7)];
    __syncthreads();

    const int o = tid >> 2, fq = tid & 3;
    for (int bi = 0; bi < 16; bi++) {
        const int bk = gb * 16 + bi;
        float l[RR];
#pragma unroll
        for (int r = 0; r < RR; r++) l[r] = lrs[bi][r];
        unsigned short hu[4], lu[4];
#pragma unroll
        for (int q = 0; q < 4; q++) {
            const int fl = fq * 4 + q;
            float v = 0.f;
#pragma unroll
            for (int r = 0; r < RR; r++) v += l[r] * bs[r][fl][o];
            bsplit(v, hu[q], lu[q]);
        }
        size_t dbase = (size_t)bk * (OO * FF) + (size_t)o * FF + f0p + fq * 4;
        uint2 hp = make_uint2((uint32_t)hu[0] | ((uint32_t)hu[1] << 16),
                              (uint32_t)hu[2] | ((uint32_t)hu[3] << 16));
        uint2 lp = make_uint2((uint32_t)lu[0] | ((uint32_t)lu[1] << 16),
                              (uint32_t)lu[2] | ((uint32_t)lu[3] << 16));
        *reinterpret_cast<uint2*>(&g_kThi[dbase]) = hp;
        *reinterpret_cast<uint2*>(&g_kTlo[dbase]) = lp;
    }
}

// ================= K4: grouped GEMM, M=64 tiles, K=32 stages, 4 CTAs/SM =================
// 18 half-tap chunks. Per stage: AH 64*80=5120, AL 5120, BH 5120, BL 5120 = 20480.
// 2 stages = 40960; rows @40960 (256B); bias @41216 (256B); total 41472 -> 4 CTAs/SM.
#define AHI_OFF 0
#define ALO_OFF 5120
#define BHI_OFF 10240
#define BLO_OFF 15360
#define STAGE_SZ 20480
#define ROWS_OFF 40960
#define BIAS_OFF 41216
#define GEMM_SMEM 41472
#define RSTB 80            // row stride bytes (64B data + 16B pad)

__global__ void __launch_bounds__(256, 4) gemm_kernel() {
    extern __shared__ char smraw[];
    int*   rows  = reinterpret_cast<int*>(smraw + ROWS_OFF);
    float* sbias = reinterpret_cast<float*>(smraw + BIAS_OFF);

    const int bk = blockIdx.x;
    const int b = bk >> 4;
    const int off = g_offs[bk + b];
    const int end = g_offs[bk + b + 1];
    const int m0 = blockIdx.y << 6;
    if (off + m0 >= end) return;
    const int nk = end - off;
    const int tid = threadIdx.x;

    if (tid < 64) {
        int i = m0 + tid;
        rows[tid] = g_perm[(b << 12) + off + (i < nk ? i : 0)];
    }
    if (tid >= 128 && tid < 192) sbias[tid - 128] = g_biasv[(bk << 6) + tid - 128];
    __syncthreads();

    const __nv_bfloat16* __restrict__ img = g_img + (((size_t)b << 12) << 7);
    const __nv_bfloat16* __restrict__ khi = g_kThi + (size_t)bk * (OO * FF);
    const __nv_bfloat16* __restrict__ klo = g_kTlo + (size_t)bk * (OO * FF);

    const uint32_t sb = smem_u32(smraw);
    const int lane = tid & 31, wid = tid >> 5;
    const int wm = (wid & 1) << 5;     // 0, 32
    const int wn = (wid >> 1) << 4;    // 0,16,32,48
    const int qr = lane >> 2;
    const int qc = lane & 3;

    uint32_t aoff[2], boff[2];
#pragma unroll
    for (int mf = 0; mf < 2; mf++)
        aoff[mf] = (uint32_t)(wm + mf * 16 + (lane & 15)) * RSTB + ((lane >> 4) << 4);
#pragma unroll
    for (int nf = 0; nf < 2; nf++)
        boff[nf] = (uint32_t)(wn + nf * 8 + (lane & 7)) * RSTB + (((lane >> 3) & 1) << 4);

    float d[2][2][4];
#pragma unroll
    for (int mf = 0; mf < 2; mf++)
#pragma unroll
        for (int nf = 0; nf < 2; nf++)
#pragma unroll
            for (int q = 0; q < 4; q++) d[mf][nf][q] = 0.f;

    // chunk ch (0..17): tap = ch>>1, half = ch&1 (channels half*32..half*32+31)
    auto load_chunk = [&](int ch, int buf) {
        const uint32_t st = sb + buf * STAGE_SZ;
        const int tap = ch >> 1;
        const int hb = (ch & 1) << 6;    // byte offset inside hi block
        const int dy = tap / 3 - 1, dx = tap % 3 - 1;
        const int kc = ch << 5;          // f' base of this chunk
        // A: 64 rows x 4 segs = 256 -> 1 per thread per array
        {
            int rid = tid >> 2, seg = tid & 3;
            int n = rows[rid];
            int yy = (n >> 6) + dy, xx = (n & 63) + dx;
            bool valid = ((unsigned)yy < 64u) && ((unsigned)xx < 64u);
            int p = valid ? ((yy << 6) + xx) : 0;
            const char* src = reinterpret_cast<const char*>(img + ((size_t)p << 7)) + hb + seg * 16;
            unsigned sz = valid ? 16u : 0u;
            CP16Z(st + AHI_OFF + rid * RSTB + seg * 16, src, sz);
            CP16Z(st + ALO_OFF + rid * RSTB + seg * 16, src + 128, sz);
        }
        // B: 64 rows x 4 segs = 256 -> 1 per thread per array
        {
            int rid = tid >> 2, seg = tid & 3;
            CP16(st + BHI_OFF + rid * RSTB + seg * 16, khi + (size_t)rid * FF + kc + seg * 8);
            CP16(st + BLO_OFF + rid * RSTB + seg * 16, klo + (size_t)rid * FF + kc + seg * 8);
        }
        CP_COMMIT();
    };

    load_chunk(0, 0);

    for (int c = 0; c < 18; c++) {
        const int buf = c & 1;
        if (c < 17) {
            load_chunk(c + 1, buf ^ 1);
            CP_WAIT(1);
        } else {
            CP_WAIT(0);
        }
        __syncthreads();

        const uint32_t st = sb + buf * STAGE_SZ;

#pragma unroll
        for (int s = 0; s < 2; s++) {
            const uint32_t so = (uint32_t)(s << 5);
            uint32_t ahi[2][4], alo[2][4], bhi[2][2], blo[2][2];
#pragma unroll
            for (int mf = 0; mf < 2; mf++) {
                LDSM_X4(ahi[mf], st + AHI_OFF + aoff[mf] + so);
                LDSM_X4(alo[mf], st + ALO_OFF + aoff[mf] + so);
            }
#pragma unroll
            for (int nf = 0; nf < 2; nf++) {
                LDSM_X2(bhi[nf], st + BHI_OFF + boff[nf] + so);
                LDSM_X2(blo[nf], st + BLO_OFF + boff[nf] + so);
            }
#pragma unroll
            for (int mf = 0; mf < 2; mf++) {
#pragma unroll
                for (int nf = 0; nf < 2; nf++) {
                    MMA_BF16(d[mf][nf], ahi[mf], bhi[nf]);
                    MMA_BF16(d[mf][nf], ahi[mf], blo[nf]);
                    MMA_BF16(d[mf][nf], alo[mf], bhi[nf]);
                }
            }
        }
        __syncthreads();
    }

#pragma unroll
    for (int mf = 0; mf < 2; mf++) {
#pragma unroll
        for (int half = 0; half < 2; half++) {
            const int r = wm + (mf << 4) + qr + (half << 3);
            if (m0 + r < nk) {
                float* dst = g_outT + ((size_t)(b << 12) + off + m0 + r) * OO;
#pragma unroll
                for (int nf = 0; nf < 2; nf++) {
                    const int o = wn + (nf << 3) + (qc << 1);
                    float2 v = make_float2(d[mf][nf][(half << 1)] + sbias[o],
                                           d[mf][nf][(half << 1) + 1] + sbias[o + 1]);
                    *reinterpret_cast<float2*>(dst + o) = v;
                }
            }
        }
    }
}

// ================= K5: un-permute to out[b][o][n] =================
__global__ void untranspose_kernel(float* __restrict__ out) {
    const int b = blockIdx.y;
    const int n = (blockIdx.x << 8) + threadIdx.x;
    const int pos = g_inv[(b << 12) + n];
    const float4* src = reinterpret_cast<const float4*>(g_outT + ((size_t)(b << 12) + pos) * OO);
    float* ob = out + ((size_t)(b << 6)) * HWN + n;
#pragma unroll
    for (int o4 = 0; o4 < 16; o4++) {
        float4 v = src[o4];
        ob[(size_t)(o4 * 4 + 0) * HWN] = v.x;
        ob[(size_t)(o4 * 4 + 1) * HWN] = v.y;
        ob[(size_t)(o4 * 4 + 2) * HWN] = v.z;
        ob[(size_t)(o4 * 4 + 3) * HWN] = v.w;
    }
}

// ================= launch (single stream, allocation-free) =================
extern "C" void kernel_launch(void* const* d_in, const int* in_sizes, int n_in,
                              void* d_out, int out_size) {
    const float* x      = (const float*)d_in[0];
    const int*   labels = (const int*)d_in[1];
    const float* lr_w1  = (const float*)d_in[2];
    const float* lr_b1  = (const float*)d_in[3];
    const float* lr_w2  = (const float*)d_in[4];
    const float* lr_b2  = (const float*)d_in[5];
    const float* lr_w3  = (const float*)d_in[6];
    const float* lr_b3  = (const float*)d_in[7];
    const float* base   = (const float*)d_in[8];
    const float* bw1    = (const float*)d_in[9];
    const float* bb1    = (const float*)d_in[10];
    const float* bw2    = (const float*)d_in[11];
    const float* bb2    = (const float*)d_in[12];
    float* out = (float*)d_out;

    cudaFuncSetAttribute(gemm_kernel, cudaFuncAttributeMaxDynamicSharedMemorySize, GEMM_SMEM);

    convert_count_kernel<<<dim3(64, 16), 256>>>(x, labels);
    centers_mlp_kernel<<<256, 576>>>(lr_w1, lr_b1, lr_w2, lr_b2, lr_w3, lr_b3,
                                     bw1, bb1, bw2, bb2);
    buildk_kernel<<<dim3(36, 16), 256>>>(base);
    gemm_kernel<<<dim3(256, 8), 256, GEMM_SMEM>>>();
    untranspose_kernel<<<dim3(16, 16), 256>>>(out);
}

// round 15
// speedup vs baseline: 1.0879x; 1.0879x over previous
#include <cuda_runtime.h>
#include <cuda_bf16.h>
#include <cstdint>
#include <cstddef>

// ---------------- problem constants ----------------
#define BB 16
#define HWN 4096
#define KC 16
#define FF 576
#define OO 64
#define RR 8
#define MLPD 32

// feature order: f' = tap*64 + c  (tap = 3*di+dj). Weights index original f = c*9+tap.

// ---------------- device scratch ----------------
__device__ __nv_bfloat16 g_img[BB * HWN * 128];      // 16.8 MB channel-last split image
__device__ __nv_bfloat16 g_kThi[BB * KC * OO * FF];  // kernels^T hi [bk][o][f']
__device__ __nv_bfloat16 g_kTlo[BB * KC * OO * FF];
__device__ float g_outT[BB * HWN * OO];              // [b][pos][o]
__device__ int   g_offs[BB * 17];
__device__ int   g_perm[BB * HWN];
__device__ int   g_inv[BB * HWN];
__device__ float g_lowrank[BB * KC * RR];
__device__ float g_biasv[BB * KC * OO];

// ---------------- helpers ----------------
__device__ __forceinline__ uint32_t smem_u32(const void* p) {
    return (uint32_t)__cvta_generic_to_shared(p);
}
#define CP16(dst, src) asm volatile("cp.async.cg.shared.global [%0], [%1], 16;" :: "r"(dst), "l"(src))
#define CP16Z(dst, src, sz) asm volatile("cp.async.cg.shared.global [%0], [%1], 16, %2;" :: "r"(dst), "l"(src), "r"(sz))
#define CP_COMMIT()    asm volatile("cp.async.commit_group;")
#define CP_WAIT(n)     asm volatile("cp.async.wait_group %0;" :: "n"(n))

__device__ __forceinline__ void bsplit(float v, unsigned short& h, unsigned short& l) {
    __nv_bfloat16 hb = __float2bfloat16(v);
    float res = v - __bfloat162float(hb);
    __nv_bfloat16 lb = __float2bfloat16(res);
    h = *reinterpret_cast<unsigned short*>(&hb);
    l = *reinterpret_cast<unsigned short*>(&lb);
}

#define MMA_BF16(d, a, b) \
    asm volatile("mma.sync.aligned.m16n8k16.row.col.f32.bf16.bf16.f32 " \
        "{%0,%1,%2,%3}, {%4,%5,%6,%7}, {%8,%9}, {%0,%1,%2,%3};" \
        : "+f"((d)[0]), "+f"((d)[1]), "+f"((d)[2]), "+f"((d)[3]) \
        : "r"((a)[0]), "r"((a)[1]), "r"((a)[2]), "r"((a)[3]), \
          "r"((b)[0]), "r"((b)[1]))

#define LDSM_X4(r, addr) \
    asm volatile("ldmatrix.sync.aligned.m8n8.x4.shared.b16 {%0,%1,%2,%3}, [%4];" \
        : "=r"((r)[0]), "=r"((r)[1]), "=r"((r)[2]), "=r"((r)[3]) : "r"(addr))
#define LDSM_X2(r, addr) \
    asm volatile("ldmatrix.sync.aligned.m8n8.x2.shared.b16 {%0,%1}, [%2];" \
        : "=r"((r)[0]), "=r"((r)[1]) : "r"(addr))

// ================= K1: convert x -> channel-last split image + count/scatter =================
// grid (64 y, 16 b), block 256
__global__ void convert_count_kernel(const float* __restrict__ x, const int* __restrict__ labels) {
    __shared__ float sm[64 * 65];
    const int y = blockIdx.x, b = blockIdx.y;
    const int tid = threadIdx.x;

    for (int idx = tid; idx < 4096; idx += 256) {
        int c = idx >> 6, xx = idx & 63;
        sm[xx * 65 + c] = x[(((size_t)(b * 64 + c)) << 12) + (y << 6) + xx];
    }
    __syncthreads();

    {
        const int xx = tid >> 2, cq = tid & 3;
        const float* row = sm + xx * 65 + cq * 16;
        unsigned short hu[16], lu[16];
#pragma unroll
        for (int i = 0; i < 16; i++) bsplit(row[i], hu[i], lu[i]);
        __nv_bfloat16* dst = g_img + (((size_t)(b << 12) + (y << 6) + xx) << 7);
        uint4 ph0, ph1, pl0, pl1;
        ph0.x = (uint32_t)hu[0] | ((uint32_t)hu[1] << 16);   ph0.y = (uint32_t)hu[2] | ((uint32_t)hu[3] << 16);
        ph0.z = (uint32_t)hu[4] | ((uint32_t)hu[5] << 16);   ph0.w = (uint32_t)hu[6] | ((uint32_t)hu[7] << 16);
        ph1.x = (uint32_t)hu[8] | ((uint32_t)hu[9] << 16);   ph1.y = (uint32_t)hu[10] | ((uint32_t)hu[11] << 16);
        ph1.z = (uint32_t)hu[12] | ((uint32_t)hu[13] << 16); ph1.w = (uint32_t)hu[14] | ((uint32_t)hu[15] << 16);
        pl0.x = (uint32_t)lu[0] | ((uint32_t)lu[1] << 16);   pl0.y = (uint32_t)lu[2] | ((uint32_t)lu[3] << 16);
        pl0.z = (uint32_t)lu[4] | ((uint32_t)lu[5] << 16);   pl0.w = (uint32_t)lu[6] | ((uint32_t)lu[7] << 16);
        pl1.x = (uint32_t)lu[8] | ((uint32_t)lu[9] << 16);   pl1.y = (uint32_t)lu[10] | ((uint32_t)lu[11] << 16);
        pl1.z = (uint32_t)lu[12] | ((uint32_t)lu[13] << 16); pl1.w = (uint32_t)lu[14] | ((uint32_t)lu[15] << 16);
        *reinterpret_cast<uint4*>(dst + cq * 16)          = ph0;
        *reinterpret_cast<uint4*>(dst + cq * 16 + 8)      = ph1;
        *reinterpret_cast<uint4*>(dst + 64 + cq * 16)     = pl0;
        *reinterpret_cast<uint4*>(dst + 64 + cq * 16 + 8) = pl1;
    }

    if (blockIdx.x == 0) {
        __shared__ int cnt[KC];
        __shared__ int offs[KC];
        const int lane = tid & 31;
        if (tid < KC) cnt[tid] = 0;
        __syncthreads();
        for (int n = tid; n < HWN; n += 256) {
            int k = labels[b * HWN + n];
            unsigned mask = __match_any_sync(0xffffffffu, k);
            if (lane == (__ffs(mask) - 1)) atomicAdd(&cnt[k], __popc(mask));
        }
        __syncthreads();
        if (tid == 0) {
            int off = 0;
            for (int k = 0; k < KC; k++) {
                g_offs[b * 17 + k] = off;
                offs[k] = off;
                off += cnt[k];
            }
            g_offs[b * 17 + 16] = off;
        }
        __syncthreads();
        if (tid < KC) cnt[tid] = offs[tid];
        __syncthreads();
        for (int n = tid; n < HWN; n += 256) {
            int k = labels[b * HWN + n];
            unsigned mask = __match_any_sync(0xffffffffu, k);
            int leader = __ffs(mask) - 1;
            int rank = __popc(mask & ((1u << lane) - 1u));
            int base = 0;
            if (lane == leader) base = atomicAdd(&cnt[k], __popc(mask));
            base = __shfl_sync(0xffffffffu, base, leader);
            g_perm[b * HWN + base + rank] = n;
            g_inv[b * HWN + n] = base + rank;
        }
    }
}

// ================= K2: centers (8-way row-parallel, uint4 gathers) + fused MLPs =================
// grid 256 (= bk), block 576 = 8 row-groups x 72 threads
__global__ void centers_mlp_kernel(const float* __restrict__ lr_w1, const float* __restrict__ lr_b1,
                                   const float* __restrict__ lr_w2, const float* __restrict__ lr_b2,
                                   const float* __restrict__ lr_w3, const float* __restrict__ lr_b3,
                                   const float* __restrict__ bw1,   const float* __restrict__ bb1,
                                   const float* __restrict__ bw2,   const float* __restrict__ bb2) {
    __shared__ float part[8][FF];
    __shared__ float cs[FF];
    __shared__ float p1[18][33], p2[18][33];
    __shared__ float h1[MLPD], h2[MLPD], t1v[MLPD];
    const int bk = blockIdx.x;
    const int b = bk >> 4;
    const int off = g_offs[bk + b];
    const int end = g_offs[bk + b + 1];
    const int nk = end - off;
    const int t = threadIdx.x;
    const int* __restrict__ pm = g_perm + (b << 12) + off;

    {
        const int rg = t / 72;
        const int ft = t - rg * 72;
        const int tap = ft >> 3;
        const int dy = tap / 3 - 1, dx = tap % 3 - 1;
        const int c8 = (ft & 7) << 3;
        const __nv_bfloat16* img = g_img + (((size_t)b << 12) << 7);
        float acc[8];
#pragma unroll
        for (int q = 0; q < 8; q++) acc[q] = 0.f;
        for (int r = rg; r < nk; r += 8) {
            int n = pm[r];
            int yy = (n >> 6) + dy, xx = (n & 63) + dx;
            if (((unsigned)yy < 64u) && ((unsigned)xx < 64u)) {
                const __nv_bfloat16* p = img + (((yy << 6) + xx) << 7) + c8;
                uint4 hp = *reinterpret_cast<const uint4*>(p);
                uint4 lp = *reinterpret_cast<const uint4*>(p + 64);
                const __nv_bfloat162* h2v = reinterpret_cast<const __nv_bfloat162*>(&hp);
                const __nv_bfloat162* l2v = reinterpret_cast<const __nv_bfloat162*>(&lp);
#pragma unroll
                for (int w = 0; w < 4; w++) {
                    float2 hv = __bfloat1622float2(h2v[w]);
                    float2 lv = __bfloat1622float2(l2v[w]);
                    acc[w * 2]     += hv.x + lv.x;
                    acc[w * 2 + 1] += hv.y + lv.y;
                }
            }
        }
        const int fb = tap * 64 + c8;
#pragma unroll
        for (int q = 0; q < 8; q++) part[rg][fb + q] = acc[q];
    }
    __syncthreads();
    if (t < 144) {
        const float inv = 1.0f / ((float)nk + 1e-6f);
#pragma unroll
        for (int q = 0; q < 4; q++) {
            int e = t * 4 + q;
            float s = part[0][e] + part[1][e] + part[2][e] + part[3][e]
                    + part[4][e] + part[5][e] + part[6][e] + part[7][e];
            cs[e] = s * inv;
        }
    }
    __syncthreads();

    {
        const int j = t & 31, prt = t >> 5;
        float s = 0.f, s2 = 0.f;
        for (int fp = prt * 32; fp < prt * 32 + 32; fp++) {
            float cv = cs[fp];
            int f = (fp & 63) * 9 + (fp >> 6);
            s  += cv * lr_w1[f * MLPD + j];
            s2 += cv * bw1[f * MLPD + j];
        }
        p1[prt][j] = s;
        p2[prt][j] = s2;
    }
    __syncthreads();
    if (t < MLPD) {
        float s = lr_b1[t], s2 = bb1[t];
#pragma unroll
        for (int p = 0; p < 18; p++) { s += p1[p][t]; s2 += p2[p][t]; }
        h1[t]  = fmaxf(s, 0.f);
        t1v[t] = fmaxf(s2, 0.f);
    }
    __syncthreads();
    if (t < MLPD) {
        float s = lr_b2[t];
        for (int i = 0; i < MLPD; i++) s += h1[i] * lr_w2[i * MLPD + t];
        h2[t] = fmaxf(s, 0.f);
    }
    __syncthreads();
    if (t < RR) {
        float s = lr_b3[t];
        for (int i = 0; i < MLPD; i++) s += h2[i] * lr_w3[i * RR + t];
        g_lowrank[bk * RR + t] = s;
    }
    if (t < OO) {
        float s = bb2[t];
        for (int i = 0; i < MLPD; i++) s += t1v[i] * bw2[i * OO + t];
        g_biasv[bk * OO + t] = s;
    }
}

// ================= K3: fabricate kernels^T in f'-order =================
__global__ void buildk_kernel(const float* __restrict__ base) {
    __shared__ float bs[RR][16][65];
    __shared__ float lrs[16][RR];
    const int fb = blockIdx.x, gb = blockIdx.y;
    const int tap = fb >> 2;
    const int cbase = (fb & 3) * 16;
    const int f0p = fb * 16;
    const int tid = threadIdx.x;

    for (int idx = tid; idx < RR * 1024; idx += 256) {
        int r = idx >> 10;
        int e = idx & 1023;
        int fl = e >> 6, o = e & 63;
        int f = (cbase + fl) * 9 + tap;
        bs[r][fl][o] = base[((size_t)(r * FF + f)) * OO + o];
    }
    if (tid < 16 * RR)
        lrs[tid >> 3][tid & 7] = g_lowrank[(gb * 16 + (tid >> 3)) * RR + (tid & 7)];
    __syncthreads();

    const int o = tid >> 2, fq = tid & 3;
    for (int bi = 0; bi < 16; bi++) {
        const int bk = gb * 16 + bi;
        float l[RR];
#pragma unroll
        for (int r = 0; r < RR; r++) l[r] = lrs[bi][r];
        unsigned short hu[4], lu[4];
#pragma unroll
        for (int q = 0; q < 4; q++) {
            const int fl = fq * 4 + q;
            float v = 0.f;
#pragma unroll
            for (int r = 0; r < RR; r++) v += l[r] * bs[r][fl][o];
            bsplit(v, hu[q], lu[q]);
        }
        size_t dbase = (size_t)bk * (OO * FF) + (size_t)o * FF + f0p + fq * 4;
        uint2 hp = make_uint2((uint32_t)hu[0] | ((uint32_t)hu[1] << 16),
                              (uint32_t)hu[2] | ((uint32_t)hu[3] << 16));
        uint2 lp = make_uint2((uint32_t)lu[0] | ((uint32_t)lu[1] << 16),
                              (uint32_t)lu[2] | ((uint32_t)lu[3] << 16));
        *reinterpret_cast<uint2*>(&g_kThi[dbase]) = hp;
        *reinterpret_cast<uint2*>(&g_kTlo[dbase]) = lp;
    }
}

// ================= K4: grouped GEMM, M=64, K=64 chunks, 3-stage single-sync pipeline =================
// Per stage: AH 64*144=9216, AL 9216, BH 9216, BL 9216 = 36864 B. 3 stages = 110592.
// rows @110592 (256B), bias @110848 (256B); total 111104 -> 2 CTAs/SM.
// One __syncthreads per chunk: wait(1); sync; issue c+2; compute c.
#define AHI_OFF 0
#define ALO_OFF 9216
#define BHI_OFF 18432
#define BLO_OFF 27648
#define STAGE_SZ 36864
#define ROWS_OFF 110592
#define BIAS_OFF 110848
#define GEMM_SMEM 111104
#define RSTB 144           // row stride in bytes (128B data + 16B pad)

__global__ void __launch_bounds__(256, 2) gemm_kernel() {
    extern __shared__ char smraw[];
    int*   rows  = reinterpret_cast<int*>(smraw + ROWS_OFF);
    float* sbias = reinterpret_cast<float*>(smraw + BIAS_OFF);

    const int bk = blockIdx.x;
    const int b = bk >> 4;
    const int off = g_offs[bk + b];
    const int end = g_offs[bk + b + 1];
    const int m0 = blockIdx.y << 6;
    if (off + m0 >= end) return;
    const int nk = end - off;
    const int tid = threadIdx.x;

    if (tid < 64) {
        int i = m0 + tid;
        rows[tid] = g_perm[(b << 12) + off + (i < nk ? i : 0)];
    }
    if (tid >= 128 && tid < 192) sbias[tid - 128] = g_biasv[(bk << 6) + tid - 128];
    __syncthreads();

    const __nv_bfloat16* __restrict__ img = g_img + (((size_t)b << 12) << 7);
    const __nv_bfloat16* __restrict__ khi = g_kThi + (size_t)bk * (OO * FF);
    const __nv_bfloat16* __restrict__ klo = g_kTlo + (size_t)bk * (OO * FF);

    const uint32_t sb = smem_u32(smraw);
    const int lane = tid & 31, wid = tid >> 5;
    const int wm = (wid & 1) << 5;     // 0, 32
    const int wn = (wid >> 1) << 4;    // 0,16,32,48
    const int qr = lane >> 2;
    const int qc = lane & 3;

    uint32_t aoff[2], boff[2];
#pragma unroll
    for (int mf = 0; mf < 2; mf++)
        aoff[mf] = (uint32_t)(wm + mf * 16 + (lane & 15)) * RSTB + ((lane >> 4) << 4);
#pragma unroll
    for (int nf = 0; nf < 2; nf++)
        boff[nf] = (uint32_t)(wn + nf * 8 + (lane & 7)) * RSTB + (((lane >> 3) & 1) << 4);

    float d[2][2][4];
#pragma unroll
    for (int mf = 0; mf < 2; mf++)
#pragma unroll
        for (int nf = 0; nf < 2; nf++)
#pragma unroll
            for (int q = 0; q < 4; q++) d[mf][nf][q] = 0.f;

    // chunk = tap (K=64). A: 64 rows x 8 segs -> 512 cp per array, 2/thread.
    auto load_chunk = [&](int tap, int buf) {
        const uint32_t st = sb + buf * STAGE_SZ;
        const int dy = tap / 3 - 1, dx = tap % 3 - 1;
        const int kc = tap << 6;
#pragma unroll
        for (int s = 0; s < 2; s++) {
            int cid = tid + (s << 8);
            int rid = cid >> 3, ch = cid & 7;
            int n = rows[rid];
            int yy = (n >> 6) + dy, xx = (n & 63) + dx;
            bool valid = ((unsigned)yy < 64u) && ((unsigned)xx < 64u);
            int p = valid ? ((yy << 6) + xx) : 0;
            const char* src = reinterpret_cast<const char*>(img + ((size_t)p << 7)) + ch * 16;
            unsigned sz = valid ? 16u : 0u;
            CP16Z(st + AHI_OFF + rid * RSTB + ch * 16, src, sz);
            CP16Z(st + ALO_OFF + rid * RSTB + ch * 16, src + 128, sz);
        }
#pragma unroll
        for (int s = 0; s < 2; s++) {
            int cid = tid + (s << 8);
            int rid = cid >> 3, ch = cid & 7;
            CP16(st + BHI_OFF + rid * RSTB + ch * 16, khi + (size_t)rid * FF + kc + ch * 8);
            CP16(st + BLO_OFF + rid * RSTB + ch * 16, klo + (size_t)rid * FF + kc + ch * 8);
        }
        CP_COMMIT();
    };

    // prologue: two chunks in flight
    load_chunk(0, 0);
    load_chunk(1, 1);

#pragma unroll 3
    for (int c = 0; c < 9; c++) {
        const int buf = c % 3;
        if (c < 7) {
            CP_WAIT(1);                 // chunk c complete (own groups)
            __syncthreads();            // publish chunk c; compute c-1 finished everywhere
            load_chunk(c + 2, (c + 2) % 3);
        } else {
            CP_WAIT(0);
            __syncthreads();
        }

        const uint32_t st = sb + buf * STAGE_SZ;

#pragma unroll
        for (int s = 0; s < 4; s++) {
            const uint32_t so = (uint32_t)(s << 5);
            uint32_t ahi[2][4], alo[2][4], bhi[2][2], blo[2][2];
#pragma unroll
            for (int mf = 0; mf < 2; mf++) {
                LDSM_X4(ahi[mf], st + AHI_OFF + aoff[mf] + so);
                LDSM_X4(alo[mf], st + ALO_OFF + aoff[mf] + so);
            }
#pragma unroll
            for (int nf = 0; nf < 2; nf++) {
                LDSM_X2(bhi[nf], st + BHI_OFF + boff[nf] + so);
                LDSM_X2(blo[nf], st + BLO_OFF + boff[nf] + so);
            }
#pragma unroll
            for (int mf = 0; mf < 2; mf++) {
#pragma unroll
                for (int nf = 0; nf < 2; nf++) {
                    MMA_BF16(d[mf][nf], ahi[mf], bhi[nf]);
                    MMA_BF16(d[mf][nf], ahi[mf], blo[nf]);
                    MMA_BF16(d[mf][nf], alo[mf], bhi[nf]);
                }
            }
        }
    }

#pragma unroll
    for (int mf = 0; mf < 2; mf++) {
#pragma unroll
        for (int half = 0; half < 2; half++) {
            const int r = wm + (mf << 4) + qr + (half << 3);
            if (m0 + r < nk) {
                float* dst = g_outT + ((size_t)(b << 12) + off + m0 + r) * OO;
#pragma unroll
                for (int nf = 0; nf < 2; nf++) {
                    const int o = wn + (nf << 3) + (qc << 1);
                    float2 v = make_float2(d[mf][nf][(half << 1)] + sbias[o],
                                           d[mf][nf][(half << 1) + 1] + sbias[o + 1]);
                    *reinterpret_cast<float2*>(dst + o) = v;
                }
            }
        }
    }
}

// ================= K5: un-permute to out[b][o][n] =================
__global__ void untranspose_kernel(float* __restrict__ out) {
    const int b = blockIdx.y;
    const int n = (blockIdx.x << 8) + threadIdx.x;
    const int pos = g_inv[(b << 12) + n];
    const float4* src = reinterpret_cast<const float4*>(g_outT + ((size_t)(b << 12) + pos) * OO);
    float* ob = out + ((size_t)(b << 6)) * HWN + n;
#pragma unroll
    for (int o4 = 0; o4 < 16; o4++) {
        float4 v = src[o4];
        ob[(size_t)(o4 * 4 + 0) * HWN] = v.x;
        ob[(size_t)(o4 * 4 + 1) * HWN] = v.y;
        ob[(size_t)(o4 * 4 + 2) * HWN] = v.z;
        ob[(size_t)(o4 * 4 + 3) * HWN] = v.w;
    }
}

// ================= launch (single stream, allocation-free) =================
extern "C" void kernel_launch(void* const* d_in, const int* in_sizes, int n_in,
                              void* d_out, int out_size) {
    const float* x      = (const float*)d_in[0];
    const int*   labels = (const int*)d_in[1];
    const float* lr_w1  = (const float*)d_in[2];
    const float* lr_b1  = (const float*)d_in[3];
    const float* lr_w2  = (const float*)d_in[4];
    const float* lr_b2  = (const float*)d_in[5];
    const float* lr_w3  = (const float*)d_in[6];
    const float* lr_b3  = (const float*)d_in[7];
    const float* base   = (const float*)d_in[8];
    const float* bw1    = (const float*)d_in[9];
    const float* bb1    = (const float*)d_in[10];
    const float* bw2    = (const float*)d_in[11];
    const float* bb2    = (const float*)d_in[12];
    float* out = (float*)d_out;

    cudaFuncSetAttribute(gemm_kernel, cudaFuncAttributeMaxDynamicSharedMemorySize, GEMM_SMEM);

    convert_count_kernel<<<dim3(64, 16), 256>>>(x, labels);
    centers_mlp_kernel<<<256, 576>>>(lr_w1, lr_b1, lr_w2, lr_b2, lr_w3, lr_b3,
                                     bw1, bb1, bw2, bb2);
    buildk_kernel<<<dim3(36, 16), 256>>>(base);
    gemm_kernel<<<dim3(256, 8), 256, GEMM_SMEM>>>();
    untranspose_kernel<<<dim3(16, 16), 256>>>(out);
}

// round 16
// speedup vs baseline: 1.0900x; 1.0019x over previous
#include <cuda_runtime.h>
#include <cuda_bf16.h>
#include <cstdint>
#include <cstddef>

// ---------------- problem constants ----------------
#define BB 16
#define HWN 4096
#define KC 16
#define FF 576
#define OO 64
#define RR 8
#define MLPD 32

// feature order: f' = tap*64 + c  (tap = 3*di+dj). Weights index original f = c*9+tap.

// ---------------- device scratch ----------------
__device__ __nv_bfloat16 g_img[BB * HWN * 128];      // 16.8 MB channel-last split image
__device__ __nv_bfloat16 g_kThi[BB * KC * OO * FF];  // kernels^T hi [bk][o][f']
__device__ __nv_bfloat16 g_kTlo[BB * KC * OO * FF];
__device__ float g_outT[BB * HWN * OO];              // [b][pos][o]
__device__ int   g_offs[BB * 17];
__device__ int   g_perm[BB * HWN];
__device__ int   g_inv[BB * HWN];
__device__ float g_lowrank[BB * KC * RR];
__device__ float g_biasv[BB * KC * OO];

// ---------------- helpers ----------------
__device__ __forceinline__ uint32_t smem_u32(const void* p) {
    return (uint32_t)__cvta_generic_to_shared(p);
}
#define CP16(dst, src) asm volatile("cp.async.cg.shared.global [%0], [%1], 16;" :: "r"(dst), "l"(src))
#define CP16Z(dst, src, sz) asm volatile("cp.async.cg.shared.global [%0], [%1], 16, %2;" :: "r"(dst), "l"(src), "r"(sz))
#define CP_COMMIT()    asm volatile("cp.async.commit_group;")
#define CP_WAIT(n)     asm volatile("cp.async.wait_group %0;" :: "n"(n))

__device__ __forceinline__ void bsplit(float v, unsigned short& h, unsigned short& l) {
    __nv_bfloat16 hb = __float2bfloat16(v);
    float res = v - __bfloat162float(hb);
    __nv_bfloat16 lb = __float2bfloat16(res);
    h = *reinterpret_cast<unsigned short*>(&hb);
    l = *reinterpret_cast<unsigned short*>(&lb);
}

#define MMA_BF16(d, a, b) \
    asm volatile("mma.sync.aligned.m16n8k16.row.col.f32.bf16.bf16.f32 " \
        "{%0,%1,%2,%3}, {%4,%5,%6,%7}, {%8,%9}, {%0,%1,%2,%3};" \
        : "+f"((d)[0]), "+f"((d)[1]), "+f"((d)[2]), "+f"((d)[3]) \
        : "r"((a)[0]), "r"((a)[1]), "r"((a)[2]), "r"((a)[3]), \
          "r"((b)[0]), "r"((b)[1]))

#define LDSM_X4(r, addr) \
    asm volatile("ldmatrix.sync.aligned.m8n8.x4.shared.b16 {%0,%1,%2,%3}, [%4];" \
        : "=r"((r)[0]), "=r"((r)[1]), "=r"((r)[2]), "=r"((r)[3]) : "r"(addr))
#define LDSM_X2(r, addr) \
    asm volatile("ldmatrix.sync.aligned.m8n8.x2.shared.b16 {%0,%1}, [%2];" \
        : "=r"((r)[0]), "=r"((r)[1]) : "r"(addr))

// ================= K1: convert x -> channel-last split image + count/scatter =================
// grid (64 y, 16 b), block 256
__global__ void convert_count_kernel(const float* __restrict__ x, const int* __restrict__ labels) {
    __shared__ float sm[64 * 65];
    const int y = blockIdx.x, b = blockIdx.y;
    const int tid = threadIdx.x;

    for (int idx = tid; idx < 4096; idx += 256) {
        int c = idx >> 6, xx = idx & 63;
        sm[xx * 65 + c] = x[(((size_t)(b * 64 + c)) << 12) + (y << 6) + xx];
    }
    __syncthreads();

    {
        const int xx = tid >> 2, cq = tid & 3;
        const float* row = sm + xx * 65 + cq * 16;
        unsigned short hu[16], lu[16];
#pragma unroll
        for (int i = 0; i < 16; i++) bsplit(row[i], hu[i], lu[i]);
        __nv_bfloat16* dst = g_img + (((size_t)(b << 12) + (y << 6) + xx) << 7);
        uint4 ph0, ph1, pl0, pl1;
        ph0.x = (uint32_t)hu[0] | ((uint32_t)hu[1] << 16);   ph0.y = (uint32_t)hu[2] | ((uint32_t)hu[3] << 16);
        ph0.z = (uint32_t)hu[4] | ((uint32_t)hu[5] << 16);   ph0.w = (uint32_t)hu[6] | ((uint32_t)hu[7] << 16);
        ph1.x = (uint32_t)hu[8] | ((uint32_t)hu[9] << 16);   ph1.y = (uint32_t)hu[10] | ((uint32_t)hu[11] << 16);
        ph1.z = (uint32_t)hu[12] | ((uint32_t)hu[13] << 16); ph1.w = (uint32_t)hu[14] | ((uint32_t)hu[15] << 16);
        pl0.x = (uint32_t)lu[0] | ((uint32_t)lu[1] << 16);   pl0.y = (uint32_t)lu[2] | ((uint32_t)lu[3] << 16);
        pl0.z = (uint32_t)lu[4] | ((uint32_t)lu[5] << 16);   pl0.w = (uint32_t)lu[6] | ((uint32_t)lu[7] << 16);
        pl1.x = (uint32_t)lu[8] | ((uint32_t)lu[9] << 16);   pl1.y = (uint32_t)lu[10] | ((uint32_t)lu[11] << 16);
        pl1.z = (uint32_t)lu[12] | ((uint32_t)lu[13] << 16); pl1.w = (uint32_t)lu[14] | ((uint32_t)lu[15] << 16);
        *reinterpret_cast<uint4*>(dst + cq * 16)          = ph0;
        *reinterpret_cast<uint4*>(dst + cq * 16 + 8)      = ph1;
        *reinterpret_cast<uint4*>(dst + 64 + cq * 16)     = pl0;
        *reinterpret_cast<uint4*>(dst + 64 + cq * 16 + 8) = pl1;
    }

    if (blockIdx.x == 0) {
        __shared__ int cnt[KC];
        __shared__ int offs[KC];
        const int lane = tid & 31;
        if (tid < KC) cnt[tid] = 0;
        __syncthreads();
        for (int n = tid; n < HWN; n += 256) {
            int k = labels[b * HWN + n];
            unsigned mask = __match_any_sync(0xffffffffu, k);
            if (lane == (__ffs(mask) - 1)) atomicAdd(&cnt[k], __popc(mask));
        }
        __syncthreads();
        if (tid == 0) {
            int off = 0;
            for (int k = 0; k < KC; k++) {
                g_offs[b * 17 + k] = off;
                offs[k] = off;
                off += cnt[k];
            }
            g_offs[b * 17 + 16] = off;
        }
        __syncthreads();
        if (tid < KC) cnt[tid] = offs[tid];
        __syncthreads();
        for (int n = tid; n < HWN; n += 256) {
            int k = labels[b * HWN + n];
            unsigned mask = __match_any_sync(0xffffffffu, k);
            int leader = __ffs(mask) - 1;
            int rank = __popc(mask & ((1u << lane) - 1u));
            int base = 0;
            if (lane == leader) base = atomicAdd(&cnt[k], __popc(mask));
            base = __shfl_sync(0xffffffffu, base, leader);
            g_perm[b * HWN + base + rank] = n;
            g_inv[b * HWN + n] = base + rank;
        }
    }
}

// ================= K2: centers (16-way row-parallel, 32B sector-aligned gathers) + MLPs =================
// grid 256 (= bk), block 576 = 16 row-groups x 36 f-threads (9 taps x 4 ch-groups of 16)
__global__ void centers_mlp_kernel(const float* __restrict__ lr_w1, const float* __restrict__ lr_b1,
                                   const float* __restrict__ lr_w2, const float* __restrict__ lr_b2,
                                   const float* __restrict__ lr_w3, const float* __restrict__ lr_b3,
                                   const float* __restrict__ bw1,   const float* __restrict__ bb1,
                                   const float* __restrict__ bw2,   const float* __restrict__ bb2) {
    __shared__ float part[16][FF];
    __shared__ float cs[FF];
    __shared__ float p1[18][33], p2[18][33];
    __shared__ float h1[MLPD], h2[MLPD], t1v[MLPD];
    const int bk = blockIdx.x;
    const int b = bk >> 4;
    const int off = g_offs[bk + b];
    const int end = g_offs[bk + b + 1];
    const int nk = end - off;
    const int t = threadIdx.x;
    const int* __restrict__ pm = g_perm + (b << 12) + off;

    {
        const int rg = t / 36;            // 0..15
        const int ft = t - rg * 36;       // 0..35
        const int tap = ft >> 2;          // 0..8
        const int dy = tap / 3 - 1, dx = tap % 3 - 1;
        const int c16 = (ft & 3) << 4;    // 0,16,32,48
        const __nv_bfloat16* img = g_img + (((size_t)b << 12) << 7);
        float acc[16];
#pragma unroll
        for (int q = 0; q < 16; q++) acc[q] = 0.f;
        for (int r = rg; r < nk; r += 16) {
            int n = pm[r];
            int yy = (n >> 6) + dy, xx = (n & 63) + dx;
            if (((unsigned)yy < 64u) && ((unsigned)xx < 64u)) {
                const __nv_bfloat16* p = img + (((yy << 6) + xx) << 7) + c16;
                uint4 h0 = *reinterpret_cast<const uint4*>(p);
                uint4 h1v4 = *reinterpret_cast<const uint4*>(p + 8);
                uint4 l0 = *reinterpret_cast<const uint4*>(p + 64);
                uint4 l1v4 = *reinterpret_cast<const uint4*>(p + 72);
                const __nv_bfloat162* ha = reinterpret_cast<const __nv_bfloat162*>(&h0);
                const __nv_bfloat162* hb = reinterpret_cast<const __nv_bfloat162*>(&h1v4);
                const __nv_bfloat162* la = reinterpret_cast<const __nv_bfloat162*>(&l0);
                const __nv_bfloat162* lb = reinterpret_cast<const __nv_bfloat162*>(&l1v4);
#pragma unroll
                for (int w = 0; w < 4; w++) {
                    float2 hv = __bfloat1622float2(ha[w]);
                    float2 lv = __bfloat1622float2(la[w]);
                    acc[w * 2]     += hv.x + lv.x;
                    acc[w * 2 + 1] += hv.y + lv.y;
                    float2 hv2 = __bfloat1622float2(hb[w]);
                    float2 lv2 = __bfloat1622float2(lb[w]);
                    acc[8 + w * 2]     += hv2.x + lv2.x;
                    acc[8 + w * 2 + 1] += hv2.y + lv2.y;
                }
            }
        }
        const int fb = tap * 64 + c16;
#pragma unroll
        for (int q = 0; q < 16; q++) part[rg][fb + q] = acc[q];
    }
    __syncthreads();
    if (t < 144) {
        const float inv = 1.0f / ((float)nk + 1e-6f);
#pragma unroll
        for (int q = 0; q < 4; q++) {
            int e = t * 4 + q;
            float s = 0.f;
#pragma unroll
            for (int p = 0; p < 16; p++) s += part[p][e];
            cs[e] = s * inv;
        }
    }
    __syncthreads();

    // layer 1 (both MLPs): 18 parts x 32 f'
    {
        const int j = t & 31, prt = t >> 5;
        float s = 0.f, s2 = 0.f;
        for (int fp = prt * 32; fp < prt * 32 + 32; fp++) {
            float cv = cs[fp];
            int f = (fp & 63) * 9 + (fp >> 6);
            s  += cv * lr_w1[f * MLPD + j];
            s2 += cv * bw1[f * MLPD + j];
        }
        p1[prt][j] = s;
        p2[prt][j] = s2;
    }
    __syncthreads();
    if (t < MLPD) {
        float s = lr_b1[t], s2 = bb1[t];
#pragma unroll
        for (int p = 0; p < 18; p++) { s += p1[p][t]; s2 += p2[p][t]; }
        h1[t]  = fmaxf(s, 0.f);
        t1v[t] = fmaxf(s2, 0.f);
    }
    __syncthreads();
    if (t < MLPD) {
        float s = lr_b2[t];
        for (int i = 0; i < MLPD; i++) s += h1[i] * lr_w2[i * MLPD + t];
        h2[t] = fmaxf(s, 0.f);
    }
    __syncthreads();
    if (t < RR) {
        float s = lr_b3[t];
        for (int i = 0; i < MLPD; i++) s += h2[i] * lr_w3[i * RR + t];
        g_lowrank[bk * RR + t] = s;
    }
    if (t < OO) {
        float s = bb2[t];
        for (int i = 0; i < MLPD; i++) s += t1v[i] * bw2[i * OO + t];
        g_biasv[bk * OO + t] = s;
    }
}

// ================= K3: fabricate kernels^T in f'-order =================
__global__ void buildk_kernel(const float* __restrict__ base) {
    __shared__ float bs[RR][16][65];
    __shared__ float lrs[16][RR];
    const int fb = blockIdx.x, gb = blockIdx.y;
    const int tap = fb >> 2;
    const int cbase = (fb & 3) * 16;
    const int f0p = fb * 16;
    const int tid = threadIdx.x;

    for (int idx = tid; idx < RR * 1024; idx += 256) {
        int r = idx >> 10;
        int e = idx & 1023;
        int fl = e >> 6, o = e & 63;
        int f = (cbase + fl) * 9 + tap;
        bs[r][fl][o] = base[((size_t)(r * FF + f)) * OO + o];
    }
    if (tid < 16 * RR)
        lrs[tid >> 3][tid & 7] = g_lowrank[(gb * 16 + (tid >> 3)) * RR + (tid & 7)];
    __syncthreads();

    const int o = tid >> 2, fq = tid & 3;
    for (int bi = 0; bi < 16; bi++) {
        const int bk = gb * 16 + bi;
        float l[RR];
#pragma unroll
        for (int r = 0; r < RR; r++) l[r] = lrs[bi][r];
        unsigned short hu[4], lu[4];
#pragma unroll
        for (int q = 0; q < 4; q++) {
            const int fl = fq * 4 + q;
            float v = 0.f;
#pragma unroll
            for (int r = 0; r < RR; r++) v += l[r] * bs[r][fl][o];
            bsplit(v, hu[q], lu[q]);
        }
        size_t dbase = (size_t)bk * (OO * FF) + (size_t)o * FF + f0p + fq * 4;
        uint2 hp = make_uint2((uint32_t)hu[0] | ((uint32_t)hu[1] << 16),
                              (uint32_t)hu[2] | ((uint32_t)hu[3] << 16));
        uint2 lp = make_uint2((uint32_t)lu[0] | ((uint32_t)lu[1] << 16),
                              (uint32_t)lu[2] | ((uint32_t)lu[3] << 16));
        *reinterpret_cast<uint2*>(&g_kThi[dbase]) = hp;
        *reinterpret_cast<uint2*>(&g_kTlo[dbase]) = lp;
    }
}

// ================= K4: grouped GEMM (R13 best config: M=64, K=64 stages, 3 CTAs/SM) =================
#define AHI_OFF 0
#define ALO_OFF 9216
#define BHI_OFF 18432
#define BLO_OFF 27648
#define STAGE_SZ 36864
#define ROWS_OFF 73728
#define BIAS_OFF 73984
#define GEMM_SMEM 74240
#define RSTB 144           // row stride in bytes (128B data + 16B pad)

__global__ void __launch_bounds__(256, 3) gemm_kernel() {
    extern __shared__ char smraw[];
    int*   rows  = reinterpret_cast<int*>(smraw + ROWS_OFF);
    float* sbias = reinterpret_cast<float*>(smraw + BIAS_OFF);

    const int bk = blockIdx.x;
    const int b = bk >> 4;
    const int off = g_offs[bk + b];
    const int end = g_offs[bk + b + 1];
    const int m0 = blockIdx.y << 6;
    if (off + m0 >= end) return;
    const int nk = end - off;
    const int tid = threadIdx.x;

    if (tid < 64) {
        int i = m0 + tid;
        rows[tid] = g_perm[(b << 12) + off + (i < nk ? i : 0)];
    }
    if (tid >= 128 && tid < 192) sbias[tid - 128] = g_biasv[(bk << 6) + tid - 128];
    __syncthreads();

    const __nv_bfloat16* __restrict__ img = g_img + (((size_t)b << 12) << 7);
    const __nv_bfloat16* __restrict__ khi = g_kThi + (size_t)bk * (OO * FF);
    const __nv_bfloat16* __restrict__ klo = g_kTlo + (size_t)bk * (OO * FF);

    const uint32_t sb = smem_u32(smraw);
    const int lane = tid & 31, wid = tid >> 5;
    const int wm = (wid & 1) << 5;     // 0, 32
    const int wn = (wid >> 1) << 4;    // 0,16,32,48
    const int qr = lane >> 2;
    const int qc = lane & 3;

    uint32_t aoff[2], boff[2];
#pragma unroll
    for (int mf = 0; mf < 2; mf++)
        aoff[mf] = (uint32_t)(wm + mf * 16 + (lane & 15)) * RSTB + ((lane >> 4) << 4);
#pragma unroll
    for (int nf = 0; nf < 2; nf++)
        boff[nf] = (uint32_t)(wn + nf * 8 + (lane & 7)) * RSTB + (((lane >> 3) & 1) << 4);

    float d[2][2][4];
#pragma unroll
    for (int mf = 0; mf < 2; mf++)
#pragma unroll
        for (int nf = 0; nf < 2; nf++)
#pragma unroll
            for (int q = 0; q < 4; q++) d[mf][nf][q] = 0.f;

    auto load_chunk = [&](int tap, int buf) {
        const uint32_t st = sb + buf * STAGE_SZ;
        const int dy = tap / 3 - 1, dx = tap % 3 - 1;
        const int kc = tap << 6;
#pragma unroll
        for (int s = 0; s < 2; s++) {
            int cid = tid + (s << 8);
            int rid = cid >> 3, ch = cid & 7;
            int n = rows[rid];
            int yy = (n >> 6) + dy, xx = (n & 63) + dx;
            bool valid = ((unsigned)yy < 64u) && ((unsigned)xx < 64u);
            int p = valid ? ((yy << 6) + xx) : 0;
            const char* src = reinterpret_cast<const char*>(img + ((size_t)p << 7)) + ch * 16;
            unsigned sz = valid ? 16u : 0u;
            CP16Z(st + AHI_OFF + rid * RSTB + ch * 16, src, sz);
            CP16Z(st + ALO_OFF + rid * RSTB + ch * 16, src + 128, sz);
        }
#pragma unroll
        for (int s = 0; s < 2; s++) {
            int cid = tid + (s << 8);
            int rid = cid >> 3, ch = cid & 7;
            CP16(st + BHI_OFF + rid * RSTB + ch * 16, khi + (size_t)rid * FF + kc + ch * 8);
            CP16(st + BLO_OFF + rid * RSTB + ch * 16, klo + (size_t)rid * FF + kc + ch * 8);
        }
        CP_COMMIT();
    };

    load_chunk(0, 0);

    for (int c = 0; c < 9; c++) {
        const int buf = c & 1;
        if (c < 8) {
            load_chunk(c + 1, buf ^ 1);
            CP_WAIT(1);
        } else {
            CP_WAIT(0);
        }
        __syncthreads();

        const uint32_t st = sb + buf * STAGE_SZ;

#pragma unroll
        for (int s = 0; s < 4; s++) {
            const uint32_t so = (uint32_t)(s << 5);
            uint32_t ahi[2][4], alo[2][4], bhi[2][2], blo[2][2];
#pragma unroll
            for (int mf = 0; mf < 2; mf++) {
                LDSM_X4(ahi[mf], st + AHI_OFF + aoff[mf] + so);
                LDSM_X4(alo[mf], st + ALO_OFF + aoff[mf] + so);
            }
#pragma unroll
            for (int nf = 0; nf < 2; nf++) {
                LDSM_X2(bhi[nf], st + BHI_OFF + boff[nf] + so);
                LDSM_X2(blo[nf], st + BLO_OFF + boff[nf] + so);
            }
#pragma unroll
            for (int mf = 0; mf < 2; mf++) {
#pragma unroll
                for (int nf = 0; nf < 2; nf++) {
                    MMA_BF16(d[mf][nf], ahi[mf], bhi[nf]);
                    MMA_BF16(d[mf][nf], ahi[mf], blo[nf]);
                    MMA_BF16(d[mf][nf], alo[mf], bhi[nf]);
                }
            }
        }
        __syncthreads();
    }

#pragma unroll
    for (int mf = 0; mf < 2; mf++) {
#pragma unroll
        for (int half = 0; half < 2; half++) {
            const int r = wm + (mf << 4) + qr + (half << 3);
            if (m0 + r < nk) {
                float* dst = g_outT + ((size_t)(b << 12) + off + m0 + r) * OO;
#pragma unroll
                for (int nf = 0; nf < 2; nf++) {
                    const int o = wn + (nf << 3) + (qc << 1);
                    float2 v = make_float2(d[mf][nf][(half << 1)] + sbias[o],
                                           d[mf][nf][(half << 1) + 1] + sbias[o + 1]);
                    *reinterpret_cast<float2*>(dst + o) = v;
                }
            }
        }
    }
}

// ================= K5: un-permute to out[b][o][n] =================
__global__ void untranspose_kernel(float* __restrict__ out) {
    const int b = blockIdx.y;
    const int n = (blockIdx.x << 8) + threadIdx.x;
    const int pos = g_inv[(b << 12) + n];
    const float4* src = reinterpret_cast<const float4*>(g_outT + ((size_t)(b << 12) + pos) * OO);
    float* ob = out + ((size_t)(b << 6)) * HWN + n;
#pragma unroll
    for (int o4 = 0; o4 < 16; o4++) {
        float4 v = src[o4];
        ob[(size_t)(o4 * 4 + 0) * HWN] = v.x;
        ob[(size_t)(o4 * 4 + 1) * HWN] = v.y;
        ob[(size_t)(o4 * 4 + 2) * HWN] = v.z;
        ob[(size_t)(o4 * 4 + 3) * HWN] = v.w;
    }
}

// ================= launch (single stream, allocation-free) =================
extern "C" void kernel_launch(void* const* d_in, const int* in_sizes, int n_in,
                              void* d_out, int out_size) {
    const float* x      = (const float*)d_in[0];
    const int*   labels = (const int*)d_in[1];
    const float* lr_w1  = (const float*)d_in[2];
    const float* lr_b1  = (const float*)d_in[3];
    const float* lr_w2  = (const float*)d_in[4];
    const float* lr_b2  = (const float*)d_in[5];
    const float* lr_w3  = (const float*)d_in[6];
    const float* lr_b3  = (const float*)d_in[7];
    const float* base   = (const float*)d_in[8];
    const float* bw1    = (const float*)d_in[9];
    const float* bb1    = (const float*)d_in[10];
    const float* bw2    = (const float*)d_in[11];
    const float* bb2    = (const float*)d_in[12];
    float* out = (float*)d_out;

    cudaFuncSetAttribute(gemm_kernel, cudaFuncAttributeMaxDynamicSharedMemorySize, GEMM_SMEM);

    convert_count_kernel<<<dim3(64, 16), 256>>>(x, labels);
    centers_mlp_kernel<<<256, 576>>>(lr_w1, lr_b1, lr_w2, lr_b2, lr_w3, lr_b3,
                                     bw1, bb1, bw2, bb2);
    buildk_kernel<<<dim3(36, 16), 256>>>(base);
    gemm_kernel<<<dim3(256, 8), 256, GEMM_SMEM>>>();
    untranspose_kernel<<<dim3(16, 16), 256>>>(out);
}